// round 11
// baseline (speedup 1.0000x reference)
#include <cuda_runtime.h>
#include <cuda_bf16.h>
#include <cstdint>

#define N_NODES 50000
#define TPB     256
#define TILE_M  64
#define NTILES  782                    // 782 * 64 = 50048
#define A_STRIDE 800                   // packed A row: 96 pairs (768B) + 32B pad
#define A_BYTES  (TILE_M * A_STRIDE)   // 51200 smem -> 4 CTAs/SM (204.8KB of 228KB)

// W fragment records: [kstep][nblock(16)][lane(32)] x 16B; lane record = {hi0,lo0,hi1,lo1}
__device__ __align__(16) unsigned char g_Wm[12 * 16 * 512];   // 98304
__device__ __align__(16) unsigned char g_Wa[16 * 16 * 512];   // 131072

__device__ __forceinline__ void add4(float4& a, const float4 b) {
    a.x += b.x; a.y += b.y; a.z += b.z; a.w += b.w;
}
__device__ __forceinline__ void pack2(float a, float b, uint32_t& hw, uint32_t& lw) {
    __nv_bfloat162 h = __floats2bfloat162_rn(a, b);
    hw = *reinterpret_cast<uint32_t*>(&h);
    float2 hf = __bfloat1622float2(h);
    __nv_bfloat162 l = __floats2bfloat162_rn(a - hf.x, b - hf.y);
    lw = *reinterpret_cast<uint32_t*>(&l);
}
__device__ __forceinline__ void mma_bf16(float c[4],
                                         uint32_t a0, uint32_t a1, uint32_t a2, uint32_t a3,
                                         uint32_t b0, uint32_t b1) {
    asm volatile(
        "mma.sync.aligned.m16n8k16.row.col.f32.bf16.bf16.f32 "
        "{%0,%1,%2,%3}, {%4,%5,%6,%7}, {%8,%9}, {%0,%1,%2,%3};"
        : "+f"(c[0]), "+f"(c[1]), "+f"(c[2]), "+f"(c[3])
        : "r"(a0), "r"(a1), "r"(a2), "r"(a3), "r"(b0), "r"(b1));
}

__device__ __forceinline__ void store_w(unsigned char* base, int o, int k,
                                        __nv_bfloat16 h, __nv_bfloat16 l) {
    const int kk = k >> 4, r = k & 15;
    const int gid = o & 7, nblock = o >> 3;
    const int tig = (r & 7) >> 1;
    const int word_off = r & 8;
    const int halfsel = r & 1;
    unsigned char* p = base + ((size_t)(kk * 16 + nblock) * 32 + gid * 4 + tig) * 16;
    *(__nv_bfloat16*)(p + word_off + halfsel * 2)     = h;
    *(__nv_bfloat16*)(p + word_off + 4 + halfsel * 2) = l;
}

// one-time: weights -> fragment-record hi/lo layout
__global__ void prep_weights(const float* __restrict__ Wm, const float* __restrict__ Wa) {
    const int i = blockIdx.x * blockDim.x + threadIdx.x;
    if (i >= 128 * 256) return;
    const int o = i >> 8, k = i & 255;
    {
        float w = Wa[o * 256 + k];
        __nv_bfloat16 h = __float2bfloat16(w);
        __nv_bfloat16 l = __float2bfloat16(w - __bfloat162float(h));
        store_w(g_Wa, o, k, h, l);
    }
    if (k < 192) {
        float w = Wm[o * 192 + k];
        __nv_bfloat16 h = __float2bfloat16(w);
        __nv_bfloat16 l = __float2bfloat16(w - __bfloat162float(h));
        store_w(g_Wm, o, k, h, l);
    }
}

// One barrier-free k16 step with hoisted pointers.
__device__ __forceinline__ void mma_kstep_p(float acc[2][4][4], const char* ar0,
                                            const uint4* wp, int koff) {
    uint2 a[2][4];
#pragma unroll
    for (int s = 0; s < 2; ++s) {
        const char* ar = ar0 + s * 16 * A_STRIDE + koff;
        a[s][0] = *(const uint2*)(ar);
        a[s][1] = *(const uint2*)(ar + 8 * A_STRIDE);
        a[s][2] = *(const uint2*)(ar + 32);
        a[s][3] = *(const uint2*)(ar + 8 * A_STRIDE + 32);
    }
#pragma unroll
    for (int t = 0; t < 4; ++t) {
        const uint4 B = __ldg(wp + t * 32);
#pragma unroll
        for (int s = 0; s < 2; ++s) {
            mma_bf16(acc[s][t], a[s][0].x, a[s][1].x, a[s][2].x, a[s][3].x, B.x, B.z);  // hi*hi
            mma_bf16(acc[s][t], a[s][0].x, a[s][1].x, a[s][2].x, a[s][3].x, B.y, B.w);  // hi*lo
            mma_bf16(acc[s][t], a[s][0].y, a[s][1].y, a[s][2].y, a[s][3].y, B.x, B.z);  // lo*hi
        }
    }
}

__global__ void __launch_bounds__(TPB, 4)
sage_fused(const float* __restrict__ nfeats, const float* __restrict__ efeats,
           const float* __restrict__ b_msg, const float* __restrict__ b_apply,
           const int* __restrict__ src_idx, float* __restrict__ out)
{
    extern __shared__ char A[];
    const int tid  = threadIdx.x;
    const int wid  = tid >> 5;
    const int lane = tid & 31;
    const int gid  = lane >> 2;
    const int tig  = lane & 3;
    const int mrow = (wid >> 2) * 32;    // 0 / 32
    const int nb   = (wid & 3) * 4;      // n8-block base
    const int base = blockIdx.x * TILE_M;

    // ---- gather phase: 8 nodes per warp, packed straight into smem A ----
    {
        const float4* nf4 = (const float4*)nfeats;
        const float4* ef4 = (const float4*)efeats;
        for (int q = 0; q < 8; ++q) {
            const int nd = wid * 8 + q;
            const int node = base + nd;
            if (node >= N_NODES) break;           // warp-uniform
            const int myidx = __ldg(src_idx + node * 16 + (lane & 15));
            float4 a0 = {0,0,0,0}, a1 = {0,0,0,0}, e0 = {0,0,0,0}, e1 = {0,0,0,0};
#pragma unroll
            for (int j = 0; j < 16; j += 4) {
                const int s0 = __shfl_sync(0xffffffffu, myidx, j);
                const int s1 = __shfl_sync(0xffffffffu, myidx, j + 1);
                const int s2 = __shfl_sync(0xffffffffu, myidx, j + 2);
                const int s3 = __shfl_sync(0xffffffffu, myidx, j + 3);
                float4 n0 = __ldg(nf4 + (size_t)s0 * 32 + lane);
                float4 n1 = __ldg(nf4 + (size_t)s1 * 32 + lane);
                float4 n2 = __ldg(nf4 + (size_t)s2 * 32 + lane);
                float4 n3 = __ldg(nf4 + (size_t)s3 * 32 + lane);
                float4 f0 = __ldg(ef4 + ((size_t)node * 16 + j + (lane >> 4)) * 16 + (lane & 15));
                float4 f1 = __ldg(ef4 + ((size_t)node * 16 + j + 2 + (lane >> 4)) * 16 + (lane & 15));
                add4(a0, n0); add4(a1, n1); add4(a0, n2); add4(a1, n3);
                add4(e0, f0); add4(e1, f1);
            }
            add4(a0, a1);
            add4(e0, e1);
            e0.x += __shfl_down_sync(0xffffffffu, e0.x, 16);
            e0.y += __shfl_down_sync(0xffffffffu, e0.y, 16);
            e0.z += __shfl_down_sync(0xffffffffu, e0.z, 16);
            e0.w += __shfl_down_sync(0xffffffffu, e0.w, 16);
            const float inv = 0.0625f;   // mean: exactly 16 in-edges per node
            char* ar = A + nd * A_STRIDE;
            uint32_t h0, l0, h1, l1;
            pack2(a0.x * inv, a0.y * inv, h0, l0);
            pack2(a0.z * inv, a0.w * inv, h1, l1);
            *(uint4*)(ar + lane * 16) = make_uint4(h0, l0, h1, l1);
            if (lane < 16) {
                pack2(e0.x * inv, e0.y * inv, h0, l0);
                pack2(e0.z * inv, e0.w * inv, h1, l1);
                *(uint4*)(ar + 512 + lane * 16) = make_uint4(h0, l0, h1, l1);
            }
        }
    }
    __syncthreads();

    float acc[2][4][4];
#pragma unroll
    for (int s = 0; s < 2; ++s)
#pragma unroll
        for (int t = 0; t < 4; ++t)
#pragma unroll
            for (int j = 0; j < 4; ++j) acc[s][t][j] = 0.f;

    const char* ar0 = A + (mrow + gid) * A_STRIDE + tig * 8;

    // ---- GEMM1: K=192, barrier-free (B via L1-resident LDG) ----
    {
        const uint4* wp = (const uint4*)g_Wm + (size_t)nb * 32 + lane;
#pragma unroll
        for (int kk = 0; kk < 12; ++kk) {
            mma_kstep_p(acc, ar0, wp, kk * 64);
            wp += 512;
        }
    }
    __syncthreads();   // all GEMM1 A-reads done before h writeback

    // ---- h = D1 + b_msg -> A pairs [0,64) ----
#pragma unroll
    for (int t = 0; t < 4; ++t) {
        const int n0 = (wid & 3) * 32 + t * 8 + 2 * tig;
        const float2 bm = __ldg((const float2*)(b_msg + n0));
#pragma unroll
        for (int s = 0; s < 2; ++s) {
            char* ar = A + (mrow + s * 16 + gid) * A_STRIDE;
            uint32_t hw, lw;
            pack2(acc[s][t][0] + bm.x, acc[s][t][1] + bm.y, hw, lw);
            *(uint2*)(ar + (n0 >> 1) * 8) = make_uint2(hw, lw);
            pack2(acc[s][t][2] + bm.x, acc[s][t][3] + bm.y, hw, lw);
            *(uint2*)(ar + 8 * A_STRIDE + (n0 >> 1) * 8) = make_uint2(hw, lw);
        }
    }
    __syncthreads();   // h visible to all warps

#pragma unroll
    for (int s = 0; s < 2; ++s)
#pragma unroll
        for (int t = 0; t < 4; ++t)
#pragma unroll
            for (int j = 0; j < 4; ++j) acc[s][t][j] = 0.f;

    // ---- GEMM2a: h x W_apply[:,128:256] (records 8..15) ----
    {
        const uint4* wp = (const uint4*)g_Wa + (size_t)(8 * 16 + nb) * 32 + lane;
#pragma unroll
        for (int kk = 0; kk < 8; ++kk) {
            mma_kstep_p(acc, ar0, wp, kk * 64);
            wp += 512;
        }
    }
    __syncthreads();   // all GEMM2a A-reads done before restage

    // ---- restage own-feature rows from nfeats (linear), pack bf16 hi/lo ----
    {
        const float4* s = (const float4*)(nfeats + (size_t)base * 128);
#pragma unroll
        for (int i = 0; i < 8; ++i) {
            const int idx = tid + i * TPB;          // 2048 float4 = 64 rows x 32
            const int row = idx >> 5, col = idx & 31;
            float4 v = {0,0,0,0};
            if (base + row < N_NODES) v = __ldg(s + idx);
            uint32_t h0, l0, h1, l1;
            pack2(v.x, v.y, h0, l0);
            pack2(v.z, v.w, h1, l1);
            char* ar = A + row * A_STRIDE;
            *(uint2*)(ar + (col * 2) * 8)     = make_uint2(h0, l0);
            *(uint2*)(ar + (col * 2 + 1) * 8) = make_uint2(h1, l1);
        }
    }
    __syncthreads();

    // ---- GEMM2b: nfeats x W_apply[:,0:128] (records 0..7), accumulate ----
    {
        const uint4* wp = (const uint4*)g_Wa + (size_t)nb * 32 + lane;
#pragma unroll
        for (int kk = 0; kk < 8; ++kk) {
            mma_kstep_p(acc, ar0, wp, kk * 64);
            wp += 512;
        }
    }

    // ---- epilogue: relu(D2 + b_apply) -> out ----
#pragma unroll
    for (int t = 0; t < 4; ++t) {
        const int n0 = (wid & 3) * 32 + t * 8 + 2 * tig;
        const float2 ba = __ldg((const float2*)(b_apply + n0));
#pragma unroll
        for (int s = 0; s < 2; ++s) {
            const int r0 = base + mrow + s * 16 + gid;
            if (r0 < N_NODES) {
                float2 v;
                v.x = fmaxf(acc[s][t][0] + ba.x, 0.f);
                v.y = fmaxf(acc[s][t][1] + ba.y, 0.f);
                *(float2*)(out + (size_t)r0 * 128 + n0) = v;
            }
            const int r1 = r0 + 8;
            if (r1 < N_NODES) {
                float2 v;
                v.x = fmaxf(acc[s][t][2] + ba.x, 0.f);
                v.y = fmaxf(acc[s][t][3] + ba.y, 0.f);
                *(float2*)(out + (size_t)r1 * 128 + n0) = v;
            }
        }
    }
}

extern "C" void kernel_launch(void* const* d_in, const int* in_sizes, int n_in,
                              void* d_out, int out_size) {
    (void)in_sizes; (void)n_in; (void)out_size;
    const float* nfeats  = (const float*)d_in[0];
    const float* efeats  = (const float*)d_in[1];
    const float* W_msg   = (const float*)d_in[2];
    const float* b_msg   = (const float*)d_in[3];
    const float* W_apply = (const float*)d_in[4];
    const float* b_apply = (const float*)d_in[5];
    const int*   src_idx = (const int*)d_in[6];
    float* out = (float*)d_out;

    cudaFuncSetAttribute(sage_fused, cudaFuncAttributeMaxDynamicSharedMemorySize, A_BYTES);

    prep_weights<<<128, 256>>>(W_msg, W_apply);
    sage_fused<<<NTILES, TPB, A_BYTES>>>(nfeats, efeats, b_msg, b_apply, src_idx, out);
}

// round 12
// speedup vs baseline: 1.6759x; 1.6759x over previous
#include <cuda_runtime.h>
#include <cuda_bf16.h>
#include <cstdint>

#define N_NODES 50000
#define TPB     256
#define TILE_M  32
#define NTILES  1564                   // 1564 * 32 = 50048
#define A_STRIDE 800                   // packed A row: 96 pairs (768B) + 32B pad
#define A_BYTES  (TILE_M * A_STRIDE)   // 25600 smem -> 4 CTAs/SM (102.4KB)

// W fragment records: [kstep][nblock(16)][lane(32)] x 16B; lane record = {hi0,lo0,hi1,lo1}
__device__ __align__(16) unsigned char g_Wm[12 * 16 * 512];   // 98304
__device__ __align__(16) unsigned char g_Wa[16 * 16 * 512];   // 131072

__device__ __forceinline__ void add4(float4& a, const float4 b) {
    a.x += b.x; a.y += b.y; a.z += b.z; a.w += b.w;
}
__device__ __forceinline__ void pack2(float a, float b, uint32_t& hw, uint32_t& lw) {
    __nv_bfloat162 h = __floats2bfloat162_rn(a, b);
    hw = *reinterpret_cast<uint32_t*>(&h);
    float2 hf = __bfloat1622float2(h);
    __nv_bfloat162 l = __floats2bfloat162_rn(a - hf.x, b - hf.y);
    lw = *reinterpret_cast<uint32_t*>(&l);
}
__device__ __forceinline__ void mma_bf16(float c[4],
                                         uint32_t a0, uint32_t a1, uint32_t a2, uint32_t a3,
                                         uint32_t b0, uint32_t b1) {
    asm volatile(
        "mma.sync.aligned.m16n8k16.row.col.f32.bf16.bf16.f32 "
        "{%0,%1,%2,%3}, {%4,%5,%6,%7}, {%8,%9}, {%0,%1,%2,%3};"
        : "+f"(c[0]), "+f"(c[1]), "+f"(c[2]), "+f"(c[3])
        : "r"(a0), "r"(a1), "r"(a2), "r"(a3), "r"(b0), "r"(b1));
}

__device__ __forceinline__ void store_w(unsigned char* base, int o, int k,
                                        __nv_bfloat16 h, __nv_bfloat16 l) {
    const int kk = k >> 4, r = k & 15;
    const int gid = o & 7, nblock = o >> 3;
    const int tig = (r & 7) >> 1;
    const int word_off = r & 8;
    const int halfsel = r & 1;
    unsigned char* p = base + ((size_t)(kk * 16 + nblock) * 32 + gid * 4 + tig) * 16;
    *(__nv_bfloat16*)(p + word_off + halfsel * 2)     = h;
    *(__nv_bfloat16*)(p + word_off + 4 + halfsel * 2) = l;
}

// one-time: weights -> fragment-record hi/lo layout
__global__ void prep_weights(const float* __restrict__ Wm, const float* __restrict__ Wa) {
    const int i = blockIdx.x * blockDim.x + threadIdx.x;
    if (i >= 128 * 256) return;
    const int o = i >> 8, k = i & 255;
    {
        float w = Wa[o * 256 + k];
        __nv_bfloat16 h = __float2bfloat16(w);
        __nv_bfloat16 l = __float2bfloat16(w - __bfloat162float(h));
        store_w(g_Wa, o, k, h, l);
    }
    if (k < 192) {
        float w = Wm[o * 192 + k];
        __nv_bfloat16 h = __float2bfloat16(w);
        __nv_bfloat16 l = __float2bfloat16(w - __bfloat162float(h));
        store_w(g_Wm, o, k, h, l);
    }
}

// One barrier-free k16 step, warp tile m16 x n32: 4 LDS.64 (A) + 4 LDG.128 (B) + 12 HMMA.
__device__ __forceinline__ void mma_kstep_p(float acc[4][4], const char* ar0,
                                            const uint4* wp, int koff) {
    const char* ar = ar0 + koff;
    uint2 a0 = *(const uint2*)(ar);
    uint2 a1 = *(const uint2*)(ar + 8 * A_STRIDE);
    uint2 a2 = *(const uint2*)(ar + 32);
    uint2 a3 = *(const uint2*)(ar + 8 * A_STRIDE + 32);
#pragma unroll
    for (int t = 0; t < 4; ++t) {
        const uint4 B = __ldg(wp + t * 32);
        mma_bf16(acc[t], a0.x, a1.x, a2.x, a3.x, B.x, B.z);  // hi*hi
        mma_bf16(acc[t], a0.x, a1.x, a2.x, a3.x, B.y, B.w);  // hi*lo
        mma_bf16(acc[t], a0.y, a1.y, a2.y, a3.y, B.x, B.z);  // lo*hi
    }
}

__global__ void __launch_bounds__(TPB, 4)
sage_fused(const float* __restrict__ nfeats, const float* __restrict__ efeats,
           const float* __restrict__ b_msg, const float* __restrict__ b_apply,
           const int* __restrict__ src_idx, float* __restrict__ out)
{
    extern __shared__ char A[];
    const int tid  = threadIdx.x;
    const int wid  = tid >> 5;
    const int lane = tid & 31;
    const int gid  = lane >> 2;
    const int tig  = lane & 3;
    const int mrow = (wid >> 2) * 16;    // 0 / 16
    const int nb   = (wid & 3) * 4;      // n8-block base
    const int base = blockIdx.x * TILE_M;

    // ---- gather phase: 4 nodes per warp, packed straight into smem A ----
    {
        const float4* nf4 = (const float4*)nfeats;
        const float4* ef4 = (const float4*)efeats;
#pragma unroll
        for (int q = 0; q < 4; ++q) {
            const int nd = wid * 4 + q;
            const int node = base + nd;
            if (node >= N_NODES) break;           // warp-uniform
            const int myidx = __ldg(src_idx + node * 16 + (lane & 15));
            float4 a0 = {0,0,0,0}, a1 = {0,0,0,0}, e0 = {0,0,0,0}, e1 = {0,0,0,0};
#pragma unroll
            for (int j = 0; j < 16; j += 4) {
                const int s0 = __shfl_sync(0xffffffffu, myidx, j);
                const int s1 = __shfl_sync(0xffffffffu, myidx, j + 1);
                const int s2 = __shfl_sync(0xffffffffu, myidx, j + 2);
                const int s3 = __shfl_sync(0xffffffffu, myidx, j + 3);
                float4 n0 = __ldg(nf4 + (size_t)s0 * 32 + lane);
                float4 n1 = __ldg(nf4 + (size_t)s1 * 32 + lane);
                float4 n2 = __ldg(nf4 + (size_t)s2 * 32 + lane);
                float4 n3 = __ldg(nf4 + (size_t)s3 * 32 + lane);
                float4 f0 = __ldg(ef4 + ((size_t)node * 16 + j + (lane >> 4)) * 16 + (lane & 15));
                float4 f1 = __ldg(ef4 + ((size_t)node * 16 + j + 2 + (lane >> 4)) * 16 + (lane & 15));
                add4(a0, n0); add4(a1, n1); add4(a0, n2); add4(a1, n3);
                add4(e0, f0); add4(e1, f1);
            }
            add4(a0, a1);
            add4(e0, e1);
            e0.x += __shfl_down_sync(0xffffffffu, e0.x, 16);
            e0.y += __shfl_down_sync(0xffffffffu, e0.y, 16);
            e0.z += __shfl_down_sync(0xffffffffu, e0.z, 16);
            e0.w += __shfl_down_sync(0xffffffffu, e0.w, 16);
            const float inv = 0.0625f;   // mean: exactly 16 in-edges per node
            char* ar = A + nd * A_STRIDE;
            uint32_t h0, l0, h1, l1;
            pack2(a0.x * inv, a0.y * inv, h0, l0);
            pack2(a0.z * inv, a0.w * inv, h1, l1);
            *(uint4*)(ar + lane * 16) = make_uint4(h0, l0, h1, l1);
            if (lane < 16) {
                pack2(e0.x * inv, e0.y * inv, h0, l0);
                pack2(e0.z * inv, e0.w * inv, h1, l1);
                *(uint4*)(ar + 512 + lane * 16) = make_uint4(h0, l0, h1, l1);
            }
        }
    }
    __syncthreads();

    float acc[4][4];
#pragma unroll
    for (int t = 0; t < 4; ++t)
#pragma unroll
        for (int j = 0; j < 4; ++j) acc[t][j] = 0.f;

    const char* ar0 = A + (mrow + gid) * A_STRIDE + tig * 8;

    // ---- GEMM1: K=192, barrier-free (B via L1-resident LDG) ----
    {
        const uint4* wp = (const uint4*)g_Wm + (size_t)nb * 32 + lane;
#pragma unroll
        for (int kk = 0; kk < 12; ++kk) {
            mma_kstep_p(acc, ar0, wp, kk * 64);
            wp += 512;
        }
    }
    __syncthreads();   // all GEMM1 A-reads done before h writeback

    // ---- h = D1 + b_msg -> A pairs [0,64) ----
#pragma unroll
    for (int t = 0; t < 4; ++t) {
        const int n0 = (wid & 3) * 32 + t * 8 + 2 * tig;
        const float2 bm = __ldg((const float2*)(b_msg + n0));
        char* ar = A + (mrow + gid) * A_STRIDE;
        uint32_t hw, lw;
        pack2(acc[t][0] + bm.x, acc[t][1] + bm.y, hw, lw);
        *(uint2*)(ar + (n0 >> 1) * 8) = make_uint2(hw, lw);
        pack2(acc[t][2] + bm.x, acc[t][3] + bm.y, hw, lw);
        *(uint2*)(ar + 8 * A_STRIDE + (n0 >> 1) * 8) = make_uint2(hw, lw);
    }
    __syncthreads();   // h visible to all warps

#pragma unroll
    for (int t = 0; t < 4; ++t)
#pragma unroll
        for (int j = 0; j < 4; ++j) acc[t][j] = 0.f;

    // ---- GEMM2a: h x W_apply[:,128:256] (records 8..15) ----
    {
        const uint4* wp = (const uint4*)g_Wa + (size_t)(8 * 16 + nb) * 32 + lane;
#pragma unroll
        for (int kk = 0; kk < 8; ++kk) {
            mma_kstep_p(acc, ar0, wp, kk * 64);
            wp += 512;
        }
    }
    __syncthreads();   // all GEMM2a A-reads done before restage

    // ---- restage own-feature rows from nfeats (linear), pack bf16 hi/lo ----
    {
        const float4* s = (const float4*)(nfeats + (size_t)base * 128);
#pragma unroll
        for (int i = 0; i < 4; ++i) {
            const int idx = tid + i * TPB;          // 1024 float4 = 32 rows x 32
            const int row = idx >> 5, col = idx & 31;
            float4 v = {0,0,0,0};
            if (base + row < N_NODES) v = __ldg(s + idx);
            uint32_t h0, l0, h1, l1;
            pack2(v.x, v.y, h0, l0);
            pack2(v.z, v.w, h1, l1);
            char* ar = A + row * A_STRIDE;
            *(uint2*)(ar + (col * 2) * 8)     = make_uint2(h0, l0);
            *(uint2*)(ar + (col * 2 + 1) * 8) = make_uint2(h1, l1);
        }
    }
    __syncthreads();

    // ---- GEMM2b: nfeats x W_apply[:,0:128] (records 0..7), accumulate ----
    {
        const uint4* wp = (const uint4*)g_Wa + (size_t)nb * 32 + lane;
#pragma unroll
        for (int kk = 0; kk < 8; ++kk) {
            mma_kstep_p(acc, ar0, wp, kk * 64);
            wp += 512;
        }
    }

    // ---- epilogue: relu(D2 + b_apply) -> out ----
#pragma unroll
    for (int t = 0; t < 4; ++t) {
        const int n0 = (wid & 3) * 32 + t * 8 + 2 * tig;
        const float2 ba = __ldg((const float2*)(b_apply + n0));
        const int r0 = base + mrow + gid;
        if (r0 < N_NODES) {
            float2 v;
            v.x = fmaxf(acc[t][0] + ba.x, 0.f);
            v.y = fmaxf(acc[t][1] + ba.y, 0.f);
            *(float2*)(out + (size_t)r0 * 128 + n0) = v;
        }
        const int r1 = r0 + 8;
        if (r1 < N_NODES) {
            float2 v;
            v.x = fmaxf(acc[t][2] + ba.x, 0.f);
            v.y = fmaxf(acc[t][3] + ba.y, 0.f);
            *(float2*)(out + (size_t)r1 * 128 + n0) = v;
        }
    }
}

extern "C" void kernel_launch(void* const* d_in, const int* in_sizes, int n_in,
                              void* d_out, int out_size) {
    (void)in_sizes; (void)n_in; (void)out_size;
    const float* nfeats  = (const float*)d_in[0];
    const float* efeats  = (const float*)d_in[1];
    const float* W_msg   = (const float*)d_in[2];
    const float* b_msg   = (const float*)d_in[3];
    const float* W_apply = (const float*)d_in[4];
    const float* b_apply = (const float*)d_in[5];
    const int*   src_idx = (const int*)d_in[6];
    float* out = (float*)d_out;

    cudaFuncSetAttribute(sage_fused, cudaFuncAttributeMaxDynamicSharedMemorySize, A_BYTES);

    prep_weights<<<128, 256>>>(W_msg, W_apply);
    sage_fused<<<NTILES, TPB, A_BYTES>>>(nfeats, efeats, b_msg, b_apply, src_idx, out);
}